// round 1
// baseline (speedup 1.0000x reference)
#include <cuda_runtime.h>

#define B_   16
#define T_   64
#define N_   22
#define D_   64
#define K_   4
#define E_   8
#define H_   64
#define FIN_ 1280
#define TW_  59
#define MTOT_ 944   // B_*TW_

// err scratch: [m=944][n=22][e=8]
__device__ float g_err[MTOT_ * N_ * E_];

// dynamic smem layout (floats):
//  h1s : [0,     4096)   64x64  [h][m], later reused as preds [m][d]
//  h2s : [4096,  8192)   64x64  [g][m]
//  Ws  : [8192, 12288)   64x64  [k][out]   (W2 then W3)
//  As  : [12288,14368)   32x65  [k][m] padded
//  Bs  : [14368,16416)   32x64  [k][h]
#define SMEM_FLOATS 16416

__global__ __launch_bounds__(256) void moe_fused_k1(
    const float* __restrict__ x,  const int* __restrict__ nb,
    const float* __restrict__ W1, const float* __restrict__ b1,
    const float* __restrict__ W2, const float* __restrict__ b2,
    const float* __restrict__ W3, const float* __restrict__ b3)
{
    extern __shared__ float sm[];
    float* h1s = sm;
    float* h2s = sm + 4096;
    float* Ws  = sm + 8192;
    float* As  = sm + 12288;
    float* Bs  = sm + 14368;

    __shared__ int rowB[64], rowT[64], nbr[4];

    const int tid = threadIdx.x;
    const int tx  = tid & 15;      // output-col group
    const int ty  = tid >> 4;      // output-row group
    const int mBase = blockIdx.x * 64;
    const int n = blockIdx.y, e = blockIdx.z;
    const int ne = n * E_ + e;

    if (tid < 64) {
        int mg = mBase + tid;
        int b  = mg / TW_;
        rowB[tid] = b;
        rowT[tid] = mg - b * TW_;
    }
    if (tid < 4) nbr[tid] = nb[n * K_ + tid];
    __syncthreads();

    // ---------------- GEMM1: h1 = relu(f @ W1 + b1), K = 1280 ----------------
    float acc[4][4];
    #pragma unroll
    for (int i = 0; i < 4; ++i)
        #pragma unroll
        for (int j = 0; j < 4; ++j) acc[i][j] = 0.f;

    const float* W1p = W1 + (long)ne * FIN_ * H_;
    const int cA = tid & 31;   // K-column within chunk
    const int mA = tid >> 5;   // base row

    for (int kc = 0; kc < FIN_; kc += 32) {
        // decode f-column -> (dt, k, d)
        int kk  = kc + cA;
        int dt  = kk >> 8;
        int rem = kk & 255;
        int nbn = nbr[rem >> 6];
        int d   = rem & 63;
        #pragma unroll
        for (int q = 0; q < 8; ++q) {
            int mloc = mA + (q << 3);
            float v = 0.f;
            int mg = mBase + mloc;
            if (mg < MTOT_) {
                int b = rowB[mloc], t = rowT[mloc];
                v = x[((((b << 6) + t + dt) * N_ + nbn) << 6) + d];
            }
            As[cA * 65 + mloc] = v;
        }
        const float4* W1p4 = (const float4*)(W1p + kc * H_);
        float4* Bs4 = (float4*)Bs;
        #pragma unroll
        for (int q = 0; q < 2; ++q) {
            int li = tid + (q << 8);
            Bs4[li] = W1p4[li];
        }
        __syncthreads();
        #pragma unroll 8
        for (int u = 0; u < 32; ++u) {
            float a0 = As[u * 65 + (ty << 2) + 0];
            float a1 = As[u * 65 + (ty << 2) + 1];
            float a2 = As[u * 65 + (ty << 2) + 2];
            float a3 = As[u * 65 + (ty << 2) + 3];
            float4 bv = ((const float4*)Bs)[(u << 4) + tx];
            acc[0][0] += a0 * bv.x; acc[0][1] += a0 * bv.y; acc[0][2] += a0 * bv.z; acc[0][3] += a0 * bv.w;
            acc[1][0] += a1 * bv.x; acc[1][1] += a1 * bv.y; acc[1][2] += a1 * bv.z; acc[1][3] += a1 * bv.w;
            acc[2][0] += a2 * bv.x; acc[2][1] += a2 * bv.y; acc[2][2] += a2 * bv.z; acc[2][3] += a2 * bv.w;
            acc[3][0] += a3 * bv.x; acc[3][1] += a3 * bv.y; acc[3][2] += a3 * bv.z; acc[3][3] += a3 * bv.w;
        }
        __syncthreads();
    }
    // bias + relu -> h1s[h][m]
    {
        const float* b1p = b1 + ne * H_;
        #pragma unroll
        for (int j = 0; j < 4; ++j) {
            float bb = b1p[(tx << 2) + j];
            #pragma unroll
            for (int i = 0; i < 4; ++i) {
                float v = acc[i][j] + bb;
                h1s[((tx << 2) + j) * 64 + (ty << 2) + i] = fmaxf(v, 0.f);
            }
        }
    }
    __syncthreads();

    // ---------------- GEMM2: h2 = relu(h1 @ W2 + b2) ----------------
    {
        const float4* W2p4 = (const float4*)(W2 + (long)ne * H_ * H_);
        float4* Ws4 = (float4*)Ws;
        #pragma unroll
        for (int q = 0; q < 4; ++q) Ws4[tid + (q << 8)] = W2p4[tid + (q << 8)];
    }
    __syncthreads();
    #pragma unroll
    for (int i = 0; i < 4; ++i)
        #pragma unroll
        for (int j = 0; j < 4; ++j) acc[i][j] = 0.f;
    #pragma unroll 8
    for (int u = 0; u < 64; ++u) {
        float a0 = h1s[(u << 6) + (ty << 2) + 0];
        float a1 = h1s[(u << 6) + (ty << 2) + 1];
        float a2 = h1s[(u << 6) + (ty << 2) + 2];
        float a3 = h1s[(u << 6) + (ty << 2) + 3];
        float4 bv = ((const float4*)Ws)[(u << 4) + tx];
        acc[0][0] += a0 * bv.x; acc[0][1] += a0 * bv.y; acc[0][2] += a0 * bv.z; acc[0][3] += a0 * bv.w;
        acc[1][0] += a1 * bv.x; acc[1][1] += a1 * bv.y; acc[1][2] += a1 * bv.z; acc[1][3] += a1 * bv.w;
        acc[2][0] += a2 * bv.x; acc[2][1] += a2 * bv.y; acc[2][2] += a2 * bv.z; acc[2][3] += a2 * bv.w;
        acc[3][0] += a3 * bv.x; acc[3][1] += a3 * bv.y; acc[3][2] += a3 * bv.z; acc[3][3] += a3 * bv.w;
    }
    {
        const float* b2p = b2 + ne * H_;
        #pragma unroll
        for (int j = 0; j < 4; ++j) {
            float bb = b2p[(tx << 2) + j];
            #pragma unroll
            for (int i = 0; i < 4; ++i) {
                float v = acc[i][j] + bb;
                h2s[((tx << 2) + j) * 64 + (ty << 2) + i] = fmaxf(v, 0.f);
            }
        }
    }
    __syncthreads();

    // ---------------- GEMM3: pred = h2 @ W3 + b3 ----------------
    {
        const float4* W3p4 = (const float4*)(W3 + (long)ne * H_ * D_);
        float4* Ws4 = (float4*)Ws;
        #pragma unroll
        for (int q = 0; q < 4; ++q) Ws4[tid + (q << 8)] = W3p4[tid + (q << 8)];
    }
    __syncthreads();
    #pragma unroll
    for (int i = 0; i < 4; ++i)
        #pragma unroll
        for (int j = 0; j < 4; ++j) acc[i][j] = 0.f;
    #pragma unroll 8
    for (int u = 0; u < 64; ++u) {
        float a0 = h2s[(u << 6) + (ty << 2) + 0];
        float a1 = h2s[(u << 6) + (ty << 2) + 1];
        float a2 = h2s[(u << 6) + (ty << 2) + 2];
        float a3 = h2s[(u << 6) + (ty << 2) + 3];
        float4 bv = ((const float4*)Ws)[(u << 4) + tx];
        acc[0][0] += a0 * bv.x; acc[0][1] += a0 * bv.y; acc[0][2] += a0 * bv.z; acc[0][3] += a0 * bv.w;
        acc[1][0] += a1 * bv.x; acc[1][1] += a1 * bv.y; acc[1][2] += a1 * bv.z; acc[1][3] += a1 * bv.w;
        acc[2][0] += a2 * bv.x; acc[2][1] += a2 * bv.y; acc[2][2] += a2 * bv.z; acc[2][3] += a2 * bv.w;
        acc[3][0] += a3 * bv.x; acc[3][1] += a3 * bv.y; acc[3][2] += a3 * bv.z; acc[3][3] += a3 * bv.w;
    }
    // store preds [m][d] (reuse h1s region)
    {
        const float* b3p = b3 + ne * D_;
        #pragma unroll
        for (int j = 0; j < 4; ++j) {
            float bb = b3p[(tx << 2) + j];
            #pragma unroll
            for (int i = 0; i < 4; ++i)
                h1s[((ty << 2) + i) * 64 + (tx << 2) + j] = acc[i][j] + bb;
        }
    }
    __syncthreads();

    // ---------------- err[m,n,e] = mean_d (pred - y)^2 ----------------
    {
        int r  = tid >> 2;            // row 0..63
        int qd = (tid & 3) << 4;      // 16-d segment
        int mg = mBase + r;
        float s = 0.f;
        if (mg < MTOT_) {
            int b = rowB[r], t = rowT[r];
            const float* yrow = x + ((((b << 6) + t + 2) * N_ + n) << 6);
            const float* prow = h1s + (r << 6);
            #pragma unroll
            for (int dd = 0; dd < 16; ++dd) {
                float diff = prow[qd + dd] - yrow[qd + dd];
                s += diff * diff;
            }
        }
        s += __shfl_xor_sync(0xffffffffu, s, 1);
        s += __shfl_xor_sync(0xffffffffu, s, 2);
        if ((tid & 3) == 0 && mg < MTOT_)
            g_err[(mg * N_ + n) * E_ + e] = s * (1.f / 64.f);
    }
}

// ---------------- reduction: total loss + expert_idx ----------------
__global__ __launch_bounds__(256) void moe_reduce_k2(float* __restrict__ out)
{
    __shared__ float red[256];
    const int tid = threadIdx.x;
    float local = 0.f;
    for (int r = tid; r < MTOT_ * N_; r += 256) {
        const float* ep = g_err + r * E_;
        float v[8];
        #pragma unroll
        for (int i = 0; i < 8; ++i) v[i] = ep[i];
        float mn = v[0];
        #pragma unroll
        for (int i = 1; i < 8; ++i) mn = fminf(mn, v[i]);
        float ex[8]; float Z = 0.f;
        #pragma unroll
        for (int i = 0; i < 8; ++i) { ex[i] = expf(mn - v[i]); Z += ex[i]; }
        float inv = 1.f / Z;
        float kl = 0.f;
        #pragma unroll
        for (int i = 0; i < 8; ++i) {
            float p = ex[i] * inv;
            kl += p * (logf(p + 1e-9f) + 2.0794415416798357f); // +log(E)
        }
        local += mn + 0.01f * kl;
    }
    red[tid] = local;
    __syncthreads();
    for (int s = 128; s > 0; s >>= 1) {
        if (tid < s) red[tid] += red[tid + s];
        __syncthreads();
    }
    if (tid == 0) out[0] = red[0] * (1.0f / 20160.0f);  // /(B * (N-1) * (T-dt_half-2))
    if (tid < B_) {
        int m = tid * TW_ + (TW_ - 1);
        const float* ep = g_err + (m * N_ + (N_ - 1)) * E_;
        float best = ep[0]; int bi = 0;
        #pragma unroll
        for (int i = 1; i < 8; ++i) {
            float vv = ep[i];
            if (vv < best) { best = vv; bi = i; }
        }
        out[1 + tid] = (float)bi;
    }
}

extern "C" void kernel_launch(void* const* d_in, const int* in_sizes, int n_in,
                              void* d_out, int out_size)
{
    const float* x  = (const float*)d_in[0];
    const int*   nb = (const int*)d_in[1];
    const float* W1 = (const float*)d_in[2];
    const float* b1 = (const float*)d_in[3];
    const float* W2 = (const float*)d_in[4];
    const float* b2 = (const float*)d_in[5];
    const float* W3 = (const float*)d_in[6];
    const float* b3 = (const float*)d_in[7];
    float* out = (float*)d_out;

    size_t smem = SMEM_FLOATS * sizeof(float);
    cudaFuncSetAttribute(moe_fused_k1, cudaFuncAttributeMaxDynamicSharedMemorySize, (int)smem);
    moe_fused_k1<<<dim3(15, N_, E_), 256, smem>>>(x, nb, W1, b1, W2, b2, W3, b3);
    moe_reduce_k2<<<1, 256>>>(out);
}

// round 9
// speedup vs baseline: 1.4262x; 1.4262x over previous
#include <cuda_runtime.h>
#include <cstdint>

#define B_    16
#define N_    22
#define E_    8
#define TW_   59
#define MTOT_ 944
#define FIN_  1280

#define NB_RED 96

__device__ float g_err[MTOT_ * N_ * E_];
__device__ float g_part[NB_RED];

// dynamic smem layout (floats):
//  As: 2 bufs x [128][33]  -> offsets 0, 4224   (reused as h [128][65] = 8320)
//  Bs: 2 bufs x [32][65]   -> offsets 8448, 10528 (reused as Ws [64][65] = 4160, and errbuf[512])
#define AS_OFF   0
#define AS_SZ    4224
#define APITCH   33
#define BS_OFF   8448
#define BS_SZ    2080
#define BPITCH   65
#define H_OFF    0
#define HPITCH   65
#define WS_OFF   8448
#define ERR_OFF  8448
#define SMEM_FLOATS 12608

__device__ __forceinline__ uint32_t tf32b(float f) {
    uint32_t u;
    asm("cvt.rna.tf32.f32 %0, %1;" : "=r"(u) : "f"(f));
    return u;
}

__device__ __forceinline__ void mma_tf32(float* c, uint32_t a0, uint32_t a1, uint32_t a2, uint32_t a3,
                                         uint32_t b0, uint32_t b1) {
    asm volatile(
        "mma.sync.aligned.m16n8k8.row.col.f32.tf32.tf32.f32 "
        "{%0,%1,%2,%3}, {%4,%5,%6,%7}, {%8,%9}, {%0,%1,%2,%3};"
        : "+f"(c[0]), "+f"(c[1]), "+f"(c[2]), "+f"(c[3])
        : "r"(a0), "r"(a1), "r"(a2), "r"(a3), "r"(b0), "r"(b1));
}

// generic warp-tile GEMM step: C[4][2][4] += A(rows 0..127) x B(cols 0..63), k8 steps
__device__ __forceinline__ void wg_gemm(const float* __restrict__ A, int apitch,
                                        const float* __restrict__ Bm, int bpitch,
                                        int k8, int wm, int wn, int lane,
                                        float C[4][2][4])
{
    const int lr = lane >> 2;       // 0..7
    const int lc = lane & 3;        // 0..3
    for (int s = 0; s < k8; ++s) {
        const int kb = s * 8;
        uint32_t b00, b01, b10, b11;
        {
            const float* bp = Bm + (kb + lc) * bpitch + wn * 16 + lr;
            b00 = __float_as_uint(bp[0]);
            b01 = __float_as_uint(bp[4 * bpitch]);
            b10 = __float_as_uint(bp[8]);
            b11 = __float_as_uint(bp[8 + 4 * bpitch]);
        }
        #pragma unroll
        for (int i = 0; i < 4; ++i) {
            const float* ap = A + (wm * 64 + i * 16 + lr) * apitch + kb + lc;
            uint32_t a0 = __float_as_uint(ap[0]);
            uint32_t a1 = __float_as_uint(ap[8 * apitch]);
            uint32_t a2 = __float_as_uint(ap[4]);
            uint32_t a3 = __float_as_uint(ap[8 * apitch + 4]);
            mma_tf32(C[i][0], a0, a1, a2, a3, b00, b01);
            mma_tf32(C[i][1], a0, a1, a2, a3, b10, b11);
        }
    }
}

__global__ __launch_bounds__(256, 2) void moe_mma_k1(
    const float* __restrict__ x,  const int* __restrict__ nb,
    const float* __restrict__ W1, const float* __restrict__ b1,
    const float* __restrict__ W2, const float* __restrict__ b2,
    const float* __restrict__ W3, const float* __restrict__ b3)
{
    extern __shared__ float sm[];
    __shared__ int rowB[128], rowT[128], nbr[4];

    const int tid  = threadIdx.x;
    const int lane = tid & 31;
    const int wid  = tid >> 5;
    const int wm   = wid >> 2;     // 0..1
    const int wn   = wid & 3;      // 0..3
    const int mBase = blockIdx.x * 128;
    const int n = blockIdx.y, e = blockIdx.z;
    const int ne = n * E_ + e;

    if (tid < 128) {
        int mg = mBase + tid;
        if (mg >= MTOT_) mg = MTOT_ - 1;   // clamp: rows beyond range compute garbage, never read
        int b = mg / TW_;
        rowB[tid] = b;
        rowT[tid] = mg - b * TW_;
    }
    if (tid < 4) nbr[tid] = nb[n * 4 + tid];
    __syncthreads();

    // ---------------- Layer 1: C = f @ W1  (K = 1280, 40 chunks of 32) ----------------
    float C[4][2][4];
    #pragma unroll
    for (int i = 0; i < 4; ++i)
        #pragma unroll
        for (int j = 0; j < 2; ++j)
            #pragma unroll
            for (int q = 0; q < 4; ++q) C[i][j][q] = 0.f;

    const float* W1p = W1 + (size_t)ne * FIN_ * 64;

    // gather roles
    const int gm = tid >> 1;            // A row 0..127
    const int gk = (tid & 1) * 16;      // A k-offset within chunk
    const int bk = tid >> 3;            // B row (k) 0..31
    const int bh = (tid & 7) * 8;       // B col base

    float4 av[4];
    float4 bv[2];

    // prefetch chunk 0
    {
        const int kk0 = gk;
        const int dt = kk0 >> 8, rem = kk0 & 255;
        const float* p = x + ((((rowB[gm] << 6) + rowT[gm] + dt) * N_ + nbr[rem >> 6]) << 6) + (rem & 63);
        #pragma unroll
        for (int q = 0; q < 4; ++q) av[q] = *(const float4*)(p + q * 4);
        const float* wq = W1p + (size_t)bk * 64 + bh;
        bv[0] = *(const float4*)(wq);
        bv[1] = *(const float4*)(wq + 4);
    }
    // store chunk 0
    {
        float* As = sm + AS_OFF;
        #pragma unroll
        for (int q = 0; q < 4; ++q) {
            As[gm * APITCH + gk + q * 4 + 0] = __uint_as_float(tf32b(av[q].x));
            As[gm * APITCH + gk + q * 4 + 1] = __uint_as_float(tf32b(av[q].y));
            As[gm * APITCH + gk + q * 4 + 2] = __uint_as_float(tf32b(av[q].z));
            As[gm * APITCH + gk + q * 4 + 3] = __uint_as_float(tf32b(av[q].w));
        }
        float* Bs = sm + BS_OFF;
        #pragma unroll
        for (int q = 0; q < 2; ++q) {
            Bs[bk * BPITCH + bh + q * 4 + 0] = __uint_as_float(tf32b(q ? bv[1].x : bv[0].x));
            Bs[bk * BPITCH + bh + q * 4 + 1] = __uint_as_float(tf32b(q ? bv[1].y : bv[0].y));
            Bs[bk * BPITCH + bh + q * 4 + 2] = __uint_as_float(tf32b(q ? bv[1].z : bv[0].z));
            Bs[bk * BPITCH + bh + q * 4 + 3] = __uint_as_float(tf32b(q ? bv[1].w : bv[0].w));
        }
    }
    __syncthreads();

    for (int c = 0; c < 40; ++c) {
        const int buf = c & 1;
        if (c < 39) {
            const int kk0 = (c + 1) * 32 + gk;
            const int dt = kk0 >> 8, rem = kk0 & 255;
            const float* p = x + ((((rowB[gm] << 6) + rowT[gm] + dt) * N_ + nbr[rem >> 6]) << 6) + (rem & 63);
            #pragma unroll
            for (int q = 0; q < 4; ++q) av[q] = *(const float4*)(p + q * 4);
            const float* wq = W1p + (size_t)(c + 1) * 32 * 64 + (size_t)bk * 64 + bh;
            bv[0] = *(const float4*)(wq);
            bv[1] = *(const float4*)(wq + 4);
        }
        wg_gemm(sm + AS_OFF + buf * AS_SZ, APITCH, sm + BS_OFF + buf * BS_SZ, BPITCH,
                4, wm, wn, lane, C);
        if (c < 39) {
            float* As = sm + AS_OFF + (buf ^ 1) * AS_SZ;
            #pragma unroll
            for (int q = 0; q < 4; ++q) {
                As[gm * APITCH + gk + q * 4 + 0] = __uint_as_float(tf32b(av[q].x));
                As[gm * APITCH + gk + q * 4 + 1] = __uint_as_float(tf32b(av[q].y));
                As[gm * APITCH + gk + q * 4 + 2] = __uint_as_float(tf32b(av[q].z));
                As[gm * APITCH + gk + q * 4 + 3] = __uint_as_float(tf32b(av[q].w));
            }
            float* Bs = sm + BS_OFF + (buf ^ 1) * BS_SZ;
            #pragma unroll
            for (int q = 0; q < 2; ++q) {
                Bs[bk * BPITCH + bh + q * 4 + 0] = __uint_as_float(tf32b(q ? bv[1].x : bv[0].x));
                Bs[bk * BPITCH + bh + q * 4 + 1] = __uint_as_float(tf32b(q ? bv[1].y : bv[0].y));
                Bs[bk * BPITCH + bh + q * 4 + 2] = __uint_as_float(tf32b(q ? bv[1].z : bv[0].z));
                Bs[bk * BPITCH + bh + q * 4 + 3] = __uint_as_float(tf32b(q ? bv[1].w : bv[0].w));
            }
            __syncthreads();
        }
    }
    __syncthreads();   // all reads of As/Bs done before overwriting with h / W2

    // ---------------- bias+relu -> h (tf32), stage W2 ----------------
    {
        const float* b1p = b1 + ne * 64;
        float* h = sm + H_OFF;
        #pragma unroll
        for (int i = 0; i < 4; ++i) {
            const int row = wm * 64 + i * 16 + (lane >> 2);
            #pragma unroll
            for (int nf = 0; nf < 2; ++nf) {
                const int col = wn * 16 + nf * 8 + 2 * (lane & 3);
                float bb0 = b1p[col], bb1 = b1p[col + 1];
                h[row * HPITCH + col]           = __uint_as_float(tf32b(fmaxf(C[i][nf][0] + bb0, 0.f)));
                h[row * HPITCH + col + 1]       = __uint_as_float(tf32b(fmaxf(C[i][nf][1] + bb1, 0.f)));
                h[(row + 8) * HPITCH + col]     = __uint_as_float(tf32b(fmaxf(C[i][nf][2] + bb0, 0.f)));
                h[(row + 8) * HPITCH + col + 1] = __uint_as_float(tf32b(fmaxf(C[i][nf][3] + bb1, 0.f)));
            }
        }
        // W2 stage: [k=64][g=64] -> Ws pitch 65
        const float* w2p = W2 + (size_t)ne * 4096;
        float* Ws = sm + WS_OFF;
        const int kr = tid >> 2;           // 0..63
        const int g0 = (tid & 3) * 16;
        #pragma unroll
        for (int q = 0; q < 4; ++q) {
            float4 v = *(const float4*)(w2p + (size_t)kr * 64 + g0 + q * 4);
            Ws[kr * BPITCH + g0 + q * 4 + 0] = __uint_as_float(tf32b(v.x));
            Ws[kr * BPITCH + g0 + q * 4 + 1] = __uint_as_float(tf32b(v.y));
            Ws[kr * BPITCH + g0 + q * 4 + 2] = __uint_as_float(tf32b(v.z));
            Ws[kr * BPITCH + g0 + q * 4 + 3] = __uint_as_float(tf32b(v.w));
        }
    }
    __syncthreads();

    // ---------------- Layer 2 ----------------
    #pragma unroll
    for (int i = 0; i < 4; ++i)
        #pragma unroll
        for (int j = 0; j < 2; ++j)
            #pragma unroll
            for (int q = 0; q < 4; ++q) C[i][j][q] = 0.f;
    wg_gemm(sm + H_OFF, HPITCH, sm + WS_OFF, BPITCH, 8, wm, wn, lane, C);
    __syncthreads();   // reads of h/Ws done

    // bias+relu -> h (overwrite), stage W3
    {
        const float* b2p = b2 + ne * 64;
        float* h = sm + H_OFF;
        #pragma unroll
        for (int i = 0; i < 4; ++i) {
            const int row = wm * 64 + i * 16 + (lane >> 2);
            #pragma unroll
            for (int nf = 0; nf < 2; ++nf) {
                const int col = wn * 16 + nf * 8 + 2 * (lane & 3);
                float bb0 = b2p[col], bb1 = b2p[col + 1];
                h[row * HPITCH + col]           = __uint_as_float(tf32b(fmaxf(C[i][nf][0] + bb0, 0.f)));
                h[row * HPITCH + col + 1]       = __uint_as_float(tf32b(fmaxf(C[i][nf][1] + bb1, 0.f)));
                h[(row + 8) * HPITCH + col]     = __uint_as_float(tf32b(fmaxf(C[i][nf][2] + bb0, 0.f)));
                h[(row + 8) * HPITCH + col + 1] = __uint_as_float(tf32b(fmaxf(C[i][nf][3] + bb1, 0.f)));
            }
        }
        const float* w3p = W3 + (size_t)ne * 4096;
        float* Ws = sm + WS_OFF;
        const int kr = tid >> 2;
        const int g0 = (tid & 3) * 16;
        #pragma unroll
        for (int q = 0; q < 4; ++q) {
            float4 v = *(const float4*)(w3p + (size_t)kr * 64 + g0 + q * 4);
            Ws[kr * BPITCH + g0 + q * 4 + 0] = __uint_as_float(tf32b(v.x));
            Ws[kr * BPITCH + g0 + q * 4 + 1] = __uint_as_float(tf32b(v.y));
            Ws[kr * BPITCH + g0 + q * 4 + 2] = __uint_as_float(tf32b(v.z));
            Ws[kr * BPITCH + g0 + q * 4 + 3] = __uint_as_float(tf32b(v.w));
        }
    }
    __syncthreads();

    // ---------------- Layer 3 ----------------
    #pragma unroll
    for (int i = 0; i < 4; ++i)
        #pragma unroll
        for (int j = 0; j < 2; ++j)
            #pragma unroll
            for (int q = 0; q < 4; ++q) C[i][j][q] = 0.f;
    wg_gemm(sm + H_OFF, HPITCH, sm + WS_OFF, BPITCH, 8, wm, wn, lane, C);
    __syncthreads();   // reads done; errbuf overlays Ws region

    // ---------------- epilogue: err = mean_d (pred - y)^2 ----------------
    {
        float* errbuf = sm + ERR_OFF;   // [128][4]
        errbuf[tid] = 0.f;
        errbuf[tid + 256] = 0.f;
        __syncthreads();

        const float* b3p = b3 + ne * 64;
        #pragma unroll
        for (int i = 0; i < 4; ++i) {
            const int rloc0 = wm * 64 + i * 16 + (lane >> 2);
            #pragma unroll
            for (int half = 0; half < 2; ++half) {
                const int rloc = rloc0 + half * 8;
                const int mg = mBase + rloc;
                float s = 0.f;
                if (mg < MTOT_) {
                    const float* y = x + ((((rowB[rloc] << 6) + rowT[rloc] + 2) * N_ + n) << 6);
                    #pragma unroll
                    for (int nf = 0; nf < 2; ++nf) {
                        const int col = wn * 16 + nf * 8 + 2 * (lane & 3);
                        float p0 = C[i][nf][half * 2 + 0] + b3p[col];
                        float p1 = C[i][nf][half * 2 + 1] + b3p[col + 1];
                        float d0 = p0 - y[col];
                        float d1 = p1 - y[col + 1];
                        s += d0 * d0 + d1 * d1;
                    }
                }
                s += __shfl_xor_sync(0xffffffffu, s, 1);
                s += __shfl_xor_sync(0xffffffffu, s, 2);
                if ((lane & 3) == 0) errbuf[rloc * 4 + wn] = s;
            }
        }
        __syncthreads();
        if (tid < 128) {
            int mg = mBase + tid;
            if (mg < MTOT_) {
                float s = errbuf[tid * 4] + errbuf[tid * 4 + 1] + errbuf[tid * 4 + 2] + errbuf[tid * 4 + 3];
                g_err[(mg * N_ + n) * E_ + e] = s * (1.f / 64.f);
            }
        }
    }
}

// ---------------- reduction stage 1: partial sums ----------------
__global__ __launch_bounds__(256) void moe_red_part()
{
    __shared__ float red[256];
    const int tid = threadIdx.x;
    const int r = blockIdx.x * 256 + tid;
    float local = 0.f;
    if (r < MTOT_ * N_) {
        const float* ep = g_err + r * E_;
        float v[8];
        #pragma unroll
        for (int i = 0; i < 8; ++i) v[i] = ep[i];
        float mn = v[0];
        #pragma unroll
        for (int i = 1; i < 8; ++i) mn = fminf(mn, v[i]);
        float ex[8]; float Z = 0.f;
        #pragma unroll
        for (int i = 0; i < 8; ++i) { ex[i] = expf(mn - v[i]); Z += ex[i]; }
        float inv = 1.f / Z;
        float kl = 0.f;
        #pragma unroll
        for (int i = 0; i < 8; ++i) {
            float p = ex[i] * inv;
            kl += p * (logf(p + 1e-9f) + 2.0794415416798357f);
        }
        local = mn + 0.01f * kl;
    }
    red[tid] = local;
    __syncthreads();
    for (int s = 128; s > 0; s >>= 1) {
        if (tid < s) red[tid] += red[tid + s];
        __syncthreads();
    }
    if (tid == 0) g_part[blockIdx.x] = red[0];
}

// ---------------- reduction stage 2: total + expert_idx ----------------
__global__ __launch_bounds__(128) void moe_red_final(float* __restrict__ out)
{
    __shared__ float red[128];
    const int tid = threadIdx.x;
    red[tid] = (tid < NB_RED) ? g_part[tid] : 0.f;
    __syncthreads();
    for (int s = 64; s > 0; s >>= 1) {
        if (tid < s) red[tid] += red[tid + s];
        __syncthreads();
    }
    if (tid == 0) out[0] = red[0] * (1.0f / 20160.0f);
    if (tid < B_) {
        int m = tid * TW_ + (TW_ - 1);
        const float* ep = g_err + (m * N_ + (N_ - 1)) * E_;
        float best = ep[0]; int bi = 0;
        #pragma unroll
        for (int i = 1; i < 8; ++i) {
            float vv = ep[i];
            if (vv < best) { best = vv; bi = i; }
        }
        out[1 + tid] = (float)bi;
    }
}

extern "C" void kernel_launch(void* const* d_in, const int* in_sizes, int n_in,
                              void* d_out, int out_size)
{
    const float* x  = (const float*)d_in[0];
    const int*   nb = (const int*)d_in[1];
    const float* W1 = (const float*)d_in[2];
    const float* b1 = (const float*)d_in[3];
    const float* W2 = (const float*)d_in[4];
    const float* b2 = (const float*)d_in[5];
    const float* W3 = (const float*)d_in[6];
    const float* b3 = (const float*)d_in[7];
    float* out = (float*)d_out;

    size_t smem = SMEM_FLOATS * sizeof(float);
    cudaFuncSetAttribute(moe_mma_k1, cudaFuncAttributeMaxDynamicSharedMemorySize, (int)smem);
    moe_mma_k1<<<dim3(8, N_, E_), 256, smem>>>(x, nb, W1, b1, W2, b2, W3, b3);
    moe_red_part<<<NB_RED, 256>>>();
    moe_red_final<<<1, 128>>>(out);
}

// round 10
// speedup vs baseline: 1.5614x; 1.0948x over previous
#include <cuda_runtime.h>
#include <cstdint>

#define B_    16
#define N_    22
#define E_    8
#define TW_   59
#define MTOT_ 944
#define FIN_  1280
#define NB_RED 96

__device__ float g_err[MTOT_ * N_ * E_];
__device__ float g_part[NB_RED];

// dynamic smem (floats), fragment-major layouts:
//  layer1 A: 2 bufs x [4 k8][8 mblk][32 lane][4]  = 2 x 4096 @ 0
//  layer1 B: 2 bufs x [4 k8][8 nblk][32 lane][2]  = 2 x 2048 @ 8192
//  layers 2/3: hF [8 k8][8 mblk][32][4] = 8192 @ 0 ; WF [8 k8][8 nblk][32][2] = 4096 @ 8192
//  errbuf 512 @ 8192 (after gemm3)
#define AS_OFF 0
#define AS_BUF 4096
#define BS_OFF 8192
#define BS_BUF 2048
#define HF_OFF 0
#define WF_OFF 8192
#define ERR_OFF 8192
#define SMEM_FLOATS 12288

__device__ __forceinline__ uint32_t tf32b(float f) {
    uint32_t u;
    asm("cvt.rna.tf32.f32 %0, %1;" : "=r"(u) : "f"(f));
    return u;
}
__device__ __forceinline__ float tf32f(float f) { return __uint_as_float(tf32b(f)); }

__device__ __forceinline__ void mma_tf32(float* c, uint32_t a0, uint32_t a1, uint32_t a2, uint32_t a3,
                                         uint32_t b0, uint32_t b1) {
    asm volatile(
        "mma.sync.aligned.m16n8k8.row.col.f32.tf32.tf32.f32 "
        "{%0,%1,%2,%3}, {%4,%5,%6,%7}, {%8,%9}, {%0,%1,%2,%3};"
        : "+f"(c[0]), "+f"(c[1]), "+f"(c[2]), "+f"(c[3])
        : "r"(a0), "r"(a1), "r"(a2), "r"(a3), "r"(b0), "r"(b1));
}

// fragment-major warp GEMM: A [k8][mblk 8][lane][4], B [k8][nblk 8][lane][2]
__device__ __forceinline__ void wg_gemm_frag(const float* __restrict__ A,
                                             const float* __restrict__ Bm,
                                             int k8cnt, int wm, int wn, int lane,
                                             float C[4][2][4])
{
    for (int s = 0; s < k8cnt; ++s) {
        float2 bf0 = *(const float2*)(Bm + s * 512 + (wn * 2 + 0) * 64 + lane * 2);
        float2 bf1 = *(const float2*)(Bm + s * 512 + (wn * 2 + 1) * 64 + lane * 2);
        uint32_t b00 = __float_as_uint(bf0.x), b01 = __float_as_uint(bf0.y);
        uint32_t b10 = __float_as_uint(bf1.x), b11 = __float_as_uint(bf1.y);
        #pragma unroll
        for (int i = 0; i < 4; ++i) {
            float4 a = *(const float4*)(A + s * 1024 + (wm * 4 + i) * 128 + lane * 4);
            mma_tf32(C[i][0], __float_as_uint(a.x), __float_as_uint(a.y),
                              __float_as_uint(a.z), __float_as_uint(a.w), b00, b01);
            mma_tf32(C[i][1], __float_as_uint(a.x), __float_as_uint(a.y),
                              __float_as_uint(a.z), __float_as_uint(a.w), b10, b11);
        }
    }
}

__global__ __launch_bounds__(256, 2) void moe_mma_k1(
    const float* __restrict__ x,  const int* __restrict__ nb,
    const float* __restrict__ W1, const float* __restrict__ b1,
    const float* __restrict__ W2, const float* __restrict__ b2,
    const float* __restrict__ W3, const float* __restrict__ b3)
{
    extern __shared__ float sm[];
    __shared__ int rbase[128];
    __shared__ int nbr[4];

    const int tid  = threadIdx.x;
    const int lane = tid & 31;
    const int wid  = tid >> 5;
    const int wm   = wid >> 2;   // 0..1
    const int wn   = wid & 3;    // 0..3
    const int lr   = lane >> 2;  // 0..7
    const int lc   = lane & 3;   // 0..3
    const int mBase = blockIdx.x * 128;
    const int n = blockIdx.y, e = blockIdx.z;
    const int ne = n * E_ + e;

    if (tid < 128) {
        int mg = mBase + tid;
        if (mg >= MTOT_) mg = MTOT_ - 1;   // clamped rows compute garbage, never read
        int b = mg / TW_;
        int t = mg - b * TW_;
        rbase[tid] = (b * 64 + t) * (N_ * 64);
    }
    if (tid < 4) nbr[tid] = nb[n * 4 + tid];
    __syncthreads();

    // staging roles: this thread owns fragment slots (k8=q, mblk=wid, lane) for A
    // and (k8=q, nblk=wid, lane) for B
    const int r0 = wid * 16 + lr;
    const int xb0 = rbase[r0];
    const int xb1 = rbase[r0 + 8];
    const int bn0 = wid * 8 + lr;
    const float* W1p = W1 + (size_t)ne * FIN_ * 64;

    float C[4][2][4];
    #pragma unroll
    for (int i = 0; i < 4; ++i)
        #pragma unroll
        for (int j = 0; j < 2; ++j)
            #pragma unroll
            for (int q = 0; q < 4; ++q) C[i][j][q] = 0.f;

    float a_r[4][4];
    float b_r[4][2];

    auto loadch = [&](int c) {
        #pragma unroll
        for (int q = 0; q < 4; ++q) {
            const int kk = c * 32 + q * 8 + lc;
            const int dt = kk >> 8, rem = kk & 255;
            const int koff = (dt * N_ + nbr[rem >> 6]) * 64 + (rem & 63);
            a_r[q][0] = x[xb0 + koff];
            a_r[q][1] = x[xb1 + koff];
            a_r[q][2] = x[xb0 + koff + 4];
            a_r[q][3] = x[xb1 + koff + 4];
            const float* wp = W1p + (size_t)kk * 64 + bn0;
            b_r[q][0] = wp[0];
            b_r[q][1] = wp[256];
        }
    };
    auto storech = [&](int buf) {
        float* As = sm + AS_OFF + buf * AS_BUF;
        float* Bs = sm + BS_OFF + buf * BS_BUF;
        #pragma unroll
        for (int q = 0; q < 4; ++q) {
            *(float4*)(As + q * 1024 + wid * 128 + lane * 4) =
                make_float4(tf32f(a_r[q][0]), tf32f(a_r[q][1]), tf32f(a_r[q][2]), tf32f(a_r[q][3]));
            *(float2*)(Bs + q * 512 + wid * 64 + lane * 2) =
                make_float2(tf32f(b_r[q][0]), tf32f(b_r[q][1]));
        }
    };

    // ---------------- Layer 1: K = 1280 in 40 chunks of 32, double-buffered ----------------
    loadch(0);
    storech(0);
    __syncthreads();
    for (int c = 0; c < 40; ++c) {
        const int buf = c & 1;
        if (c < 39) loadch(c + 1);
        wg_gemm_frag(sm + AS_OFF + buf * AS_BUF, sm + BS_OFF + buf * BS_BUF, 4, wm, wn, lane, C);
        if (c < 39) {
            storech(buf ^ 1);
            __syncthreads();
        }
    }
    __syncthreads();   // all frag reads done before overwriting with hF / WF

    auto write_h = [&](const float* bp) {
        #pragma unroll
        for (int i = 0; i < 4; ++i) {
            #pragma unroll
            for (int nf = 0; nf < 2; ++nf) {
                const int col = wn * 16 + nf * 8 + 2 * lc;
                const float bb0 = bp[col], bb1 = bp[col + 1];
                const float v0 = tf32f(fmaxf(C[i][nf][0] + bb0, 0.f));
                const float v1 = tf32f(fmaxf(C[i][nf][1] + bb1, 0.f));
                const float v2 = tf32f(fmaxf(C[i][nf][2] + bb0, 0.f));
                const float v3 = tf32f(fmaxf(C[i][nf][3] + bb1, 0.f));
                const int addr = (wn * 2 + nf) * 1024 + (wm * 4 + i) * 128
                               + (lr * 4 + 2 * (lc & 1)) * 4 + 2 * (lc >> 1);
                *(float2*)(sm + HF_OFF + addr)     = make_float2(v0, v2);
                *(float2*)(sm + HF_OFF + addr + 4) = make_float2(v1, v3);
            }
        }
    };
    auto stage_W = [&](const float* Wp) {
        #pragma unroll
        for (int q = 0; q < 8; ++q) {
            const float* wp = Wp + (q * 8 + lc) * 64 + bn0;
            *(float2*)(sm + WF_OFF + q * 512 + wid * 64 + lane * 2) =
                make_float2(tf32f(wp[0]), tf32f(wp[256]));
        }
    };
    auto zeroC = [&]() {
        #pragma unroll
        for (int i = 0; i < 4; ++i)
            #pragma unroll
            for (int j = 0; j < 2; ++j)
                #pragma unroll
                for (int q = 0; q < 4; ++q) C[i][j][q] = 0.f;
    };

    // ---------------- Layer 2 ----------------
    write_h(b1 + ne * 64);
    stage_W(W2 + (size_t)ne * 4096);
    __syncthreads();
    zeroC();
    wg_gemm_frag(sm + HF_OFF, sm + WF_OFF, 8, wm, wn, lane, C);
    __syncthreads();

    // ---------------- Layer 3 ----------------
    write_h(b2 + ne * 64);
    stage_W(W3 + (size_t)ne * 4096);
    __syncthreads();
    zeroC();
    wg_gemm_frag(sm + HF_OFF, sm + WF_OFF, 8, wm, wn, lane, C);
    __syncthreads();

    // ---------------- epilogue: err = mean_d (pred - y)^2 ----------------
    {
        float* errbuf = sm + ERR_OFF;   // [128][4]
        errbuf[tid] = 0.f;
        errbuf[tid + 256] = 0.f;
        __syncthreads();

        const float* b3p = b3 + ne * 64;
        #pragma unroll
        for (int i = 0; i < 4; ++i) {
            const int rloc0 = wm * 64 + i * 16 + lr;
            #pragma unroll
            for (int half = 0; half < 2; ++half) {
                const int rloc = rloc0 + half * 8;
                const int mg = mBase + rloc;
                float s = 0.f;
                if (mg < MTOT_) {
                    const float* y = x + rbase[rloc] + (2 * N_ + n) * 64;
                    #pragma unroll
                    for (int nf = 0; nf < 2; ++nf) {
                        const int col = wn * 16 + nf * 8 + 2 * lc;
                        float p0 = C[i][nf][half * 2 + 0] + b3p[col];
                        float p1 = C[i][nf][half * 2 + 1] + b3p[col + 1];
                        float d0 = p0 - y[col];
                        float d1 = p1 - y[col + 1];
                        s += d0 * d0 + d1 * d1;
                    }
                }
                s += __shfl_xor_sync(0xffffffffu, s, 1);
                s += __shfl_xor_sync(0xffffffffu, s, 2);
                if (lc == 0) errbuf[rloc * 4 + wn] = s;
            }
        }
        __syncthreads();
        if (tid < 128) {
            int mg = mBase + tid;
            if (mg < MTOT_) {
                float s = errbuf[tid * 4] + errbuf[tid * 4 + 1] + errbuf[tid * 4 + 2] + errbuf[tid * 4 + 3];
                g_err[(mg * N_ + n) * E_ + e] = s * (1.f / 64.f);
            }
        }
    }
}

// ---------------- reduction stage 1: partial sums ----------------
__global__ __launch_bounds__(256) void moe_red_part()
{
    __shared__ float red[256];
    const int tid = threadIdx.x;
    const int r = blockIdx.x * 256 + tid;
    float local = 0.f;
    if (r < MTOT_ * N_) {
        const float* ep = g_err + r * E_;
        float v[8];
        #pragma unroll
        for (int i = 0; i < 8; ++i) v[i] = ep[i];
        float mn = v[0];
        #pragma unroll
        for (int i = 1; i < 8; ++i) mn = fminf(mn, v[i]);
        float ex[8]; float Z = 0.f;
        #pragma unroll
        for (int i = 0; i < 8; ++i) { ex[i] = expf(mn - v[i]); Z += ex[i]; }
        float inv = 1.f / Z;
        float kl = 0.f;
        #pragma unroll
        for (int i = 0; i < 8; ++i) {
            float p = ex[i] * inv;
            kl += p * (logf(p + 1e-9f) + 2.0794415416798357f);
        }
        local = mn + 0.01f * kl;
    }
    red[tid] = local;
    __syncthreads();
    for (int s = 128; s > 0; s >>= 1) {
        if (tid < s) red[tid] += red[tid + s];
        __syncthreads();
    }
    if (tid == 0) g_part[blockIdx.x] = red[0];
}

// ---------------- reduction stage 2: total + expert_idx ----------------
__global__ __launch_bounds__(128) void moe_red_final(float* __restrict__ out)
{
    __shared__ float red[128];
    const int tid = threadIdx.x;
    red[tid] = (tid < NB_RED) ? g_part[tid] : 0.f;
    __syncthreads();
    for (int s = 64; s > 0; s >>= 1) {
        if (tid < s) red[tid] += red[tid + s];
        __syncthreads();
    }
    if (tid == 0) out[0] = red[0] * (1.0f / 20160.0f);
    if (tid < B_) {
        int m = tid * TW_ + (TW_ - 1);
        const float* ep = g_err + (m * N_ + (N_ - 1)) * E_;
        float best = ep[0]; int bi = 0;
        #pragma unroll
        for (int i = 1; i < 8; ++i) {
            float vv = ep[i];
            if (vv < best) { best = vv; bi = i; }
        }
        out[1 + tid] = (float)bi;
    }
}

extern "C" void kernel_launch(void* const* d_in, const int* in_sizes, int n_in,
                              void* d_out, int out_size)
{
    const float* x  = (const float*)d_in[0];
    const int*   nb = (const int*)d_in[1];
    const float* W1 = (const float*)d_in[2];
    const float* b1 = (const float*)d_in[3];
    const float* W2 = (const float*)d_in[4];
    const float* b2 = (const float*)d_in[5];
    const float* W3 = (const float*)d_in[6];
    const float* b3 = (const float*)d_in[7];
    float* out = (float*)d_out;

    size_t smem = SMEM_FLOATS * sizeof(float);
    cudaFuncSetAttribute(moe_mma_k1, cudaFuncAttributeMaxDynamicSharedMemorySize, (int)smem);
    moe_mma_k1<<<dim3(8, N_, E_), 256, smem>>>(x, nb, W1, b1, W2, b2, W3, b3);
    moe_red_part<<<NB_RED, 256>>>();
    moe_red_final<<<1, 128>>>(out);
}

// round 11
// speedup vs baseline: 3.2562x; 2.0854x over previous
#include <cuda_runtime.h>
#include <cstdint>

#define B_    16
#define N_    22
#define E_    8
#define TW_   59
#define MTOT_ 944
#define FIN_  1280
#define NB_RED 96
#define NE_   176
#define K8_   160
#define MT_   8

__device__ float g_err[MTOT_ * N_ * E_];
__device__ float g_part[NB_RED];

// fragment-major scratch
__device__ float g_F[(size_t)MT_ * N_ * K8_ * 1024];   // [mt][n][s][mb 8][lane 32][4]  (115 MB)
__device__ float g_W1F[(size_t)NE_ * K8_ * 512];       // [ne][s 160][nb 8][lane 32][2] (57.7 MB)
__device__ float g_W2F[NE_ * 8 * 512];                 // [ne][s 8][nb][lane][2]
__device__ float g_W3F[NE_ * 8 * 512];

__device__ __forceinline__ uint32_t tf32b(float f) {
    uint32_t u;
    asm("cvt.rna.tf32.f32 %0, %1;" : "=r"(u) : "f"(f));
    return u;
}
__device__ __forceinline__ float tf32f(float f) { return __uint_as_float(tf32b(f)); }

__device__ __forceinline__ void mma_tf32(float* c, uint32_t a0, uint32_t a1, uint32_t a2, uint32_t a3,
                                         uint32_t b0, uint32_t b1) {
    asm volatile(
        "mma.sync.aligned.m16n8k8.row.col.f32.tf32.tf32.f32 "
        "{%0,%1,%2,%3}, {%4,%5,%6,%7}, {%8,%9}, {%0,%1,%2,%3};"
        : "+f"(c[0]), "+f"(c[1]), "+f"(c[2]), "+f"(c[3])
        : "r"(a0), "r"(a1), "r"(a2), "r"(a3), "r"(b0), "r"(b1));
}

// ---------------- prep 1: materialize f in fragment-major layout ----------------
__global__ __launch_bounds__(256) void fgen(const float* __restrict__ x, const int* __restrict__ nb)
{
    size_t idx = (size_t)blockIdx.x * 256 + threadIdx.x;      // float4 index
    int lane = (int)(idx & 31);
    size_t r = idx >> 5;
    int mb = (int)(r & 7); r >>= 3;
    int s  = (int)(r % K8_); r /= K8_;
    int n  = (int)(r % N_);
    int mt = (int)(r / N_);
    if (mt >= MT_) return;
    const int lr = lane >> 2, lc = lane & 3;

    int m0 = mt * 128 + mb * 16 + lr;
    int m1 = m0 + 8;
    if (m0 >= MTOT_) m0 = MTOT_ - 1;
    if (m1 >= MTOT_) m1 = MTOT_ - 1;
    int b0 = m0 / TW_, t0 = m0 - b0 * TW_;
    int b1 = m1 / TW_, t1 = m1 - b1 * TW_;
    int xb0 = (b0 * 64 + t0) * (N_ * 64);
    int xb1 = (b1 * 64 + t1) * (N_ * 64);

    int k = s * 8 + lc;
    int dt = k >> 8, rem = k & 255;
    int nbn = nb[n * 4 + (rem >> 6)];
    int koff = (dt * N_ + nbn) * 64 + (rem & 63);   // k+4 stays in same block

    float4 v;
    v.x = tf32f(x[xb0 + koff]);
    v.y = tf32f(x[xb1 + koff]);
    v.z = tf32f(x[xb0 + koff + 4]);
    v.w = tf32f(x[xb1 + koff + 4]);
    *(float4*)&g_F[idx * 4] = v;
}

// ---------------- prep 2: W1/W2/W3 -> fragment-major ----------------
#define CNT1 (NE_ * K8_ * 256)
#define CNT2 (NE_ * 8 * 256)
__global__ __launch_bounds__(256) void wtrans(const float* __restrict__ W1,
                                              const float* __restrict__ W2,
                                              const float* __restrict__ W3)
{
    size_t idx = (size_t)blockIdx.x * 256 + threadIdx.x;      // float2 index
    if (idx < (size_t)CNT1) {
        int lane = (int)(idx & 31);
        size_t r = idx >> 5;
        int nbk = (int)(r & 7); r >>= 3;
        int s = (int)(r % K8_);
        int ne = (int)(r / K8_);
        int k = s * 8 + (lane & 3);
        int h = nbk * 8 + (lane >> 2);
        const float* src = W1 + ((size_t)ne * FIN_ + k) * 64 + h;
        g_W1F[idx * 2]     = tf32f(src[0]);
        g_W1F[idx * 2 + 1] = tf32f(src[256]);       // k+4
        return;
    }
    idx -= CNT1;
    if (idx < (size_t)(2 * CNT2)) {
        int which = (int)(idx / CNT2);
        size_t id2 = idx % CNT2;
        int lane = (int)(id2 & 31);
        size_t r = id2 >> 5;
        int nbk = (int)(r & 7); r >>= 3;
        int s = (int)(r % 8);
        int ne = (int)(r / 8);
        int k = s * 8 + (lane & 3);
        int h = nbk * 8 + (lane >> 2);
        const float* W = which ? W3 : W2;
        float* Wf = which ? g_W3F : g_W2F;
        const float* src = W + ((size_t)ne * 64 + k) * 64 + h;
        Wf[id2 * 2]     = tf32f(src[0]);
        Wf[id2 * 2 + 1] = tf32f(src[256]);
    }
}

// ---------------- main: 3-layer MLP + err ----------------
__global__ __launch_bounds__(256, 2) void moe_main(
    const float* __restrict__ x,
    const float* __restrict__ b1, const float* __restrict__ b2, const float* __restrict__ b3)
{
    extern __shared__ float sm[];   // h fragments: [s 8][mb 8][lane][4] = 8192 floats; errbuf overlay
    const int tid = threadIdx.x, lane = tid & 31, wid = tid >> 5;
    const int wm = wid >> 2, wn = wid & 3, lr = lane >> 2, lc = lane & 3;
    const int ne = blockIdx.x;
    const int n = ne >> 3, e = ne & 7;
    const int mt = blockIdx.y;
    const int mBase = mt * 128;

    float C[4][2][4];
    auto zeroC = [&]() {
        #pragma unroll
        for (int i = 0; i < 4; ++i)
            #pragma unroll
            for (int j = 0; j < 2; ++j)
                #pragma unroll
                for (int q = 0; q < 4; ++q) C[i][j][q] = 0.f;
    };
    auto MMA8 = [&](float4 a[4], float2 b[2]) {
        uint32_t b00 = __float_as_uint(b[0].x), b01 = __float_as_uint(b[0].y);
        uint32_t b10 = __float_as_uint(b[1].x), b11 = __float_as_uint(b[1].y);
        #pragma unroll
        for (int i = 0; i < 4; ++i) {
            mma_tf32(C[i][0], __float_as_uint(a[i].x), __float_as_uint(a[i].y),
                              __float_as_uint(a[i].z), __float_as_uint(a[i].w), b00, b01);
            mma_tf32(C[i][1], __float_as_uint(a[i].x), __float_as_uint(a[i].y),
                              __float_as_uint(a[i].z), __float_as_uint(a[i].w), b10, b11);
        }
    };

    // ---------- Layer 1: direct-from-gmem fragments, no smem, no syncs ----------
    zeroC();
    {
        const float* fA = g_F + ((size_t)(mt * N_ + n)) * (K8_ * 1024) + (wm * 4) * 128 + lane * 4;
        const float* fB = g_W1F + (size_t)ne * (K8_ * 512) + (wn * 2) * 64 + lane * 2;
        float4 a0[4], a1[4];
        float2 c0[2], c1[2];
        auto LD = [&](int s, float4 a[4], float2 b[2]) {
            const float* pa = fA + (size_t)s * 1024;
            #pragma unroll
            for (int i = 0; i < 4; ++i) a[i] = *(const float4*)(pa + i * 128);
            const float* pb = fB + (size_t)s * 512;
            b[0] = *(const float2*)(pb);
            b[1] = *(const float2*)(pb + 64);
        };
        LD(0, a0, c0);
        for (int s = 0; s < K8_; s += 2) {
            LD(s + 1, a1, c1);
            MMA8(a0, c0);
            if (s + 2 < K8_) LD(s + 2, a0, c0);
            MMA8(a1, c1);
        }
    }

    // write h fragments (bias+relu+tf32) into smem
    auto write_h = [&](const float* bp) {
        #pragma unroll
        for (int i = 0; i < 4; ++i)
            #pragma unroll
            for (int nf = 0; nf < 2; ++nf)
                #pragma unroll
                for (int q = 0; q < 4; ++q) {
                    int ncol = wn * 16 + nf * 8 + 2 * lc + (q & 1);
                    float v = tf32f(fmaxf(C[i][nf][q] + bp[ncol], 0.f));
                    int addr = (wn * 2 + nf) * 1024 + (wm * 4 + i) * 128
                             + (lr * 4 + 2 * (lc & 1) + (q & 1)) * 4
                             + ((q >> 1) & 1) + 2 * (lc >> 1);
                    sm[addr] = v;
                }
    };
    auto gemm_sm = [&](const float* WF) {
        zeroC();
        const float* fb = WF + (wn * 2) * 64 + lane * 2;
        #pragma unroll
        for (int s = 0; s < 8; ++s) {
            float4 a[4];
            float2 b[2];
            const float* pa = sm + s * 1024 + (wm * 4) * 128 + lane * 4;
            #pragma unroll
            for (int i = 0; i < 4; ++i) a[i] = *(const float4*)(pa + i * 128);
            b[0] = *(const float2*)(fb + s * 512);
            b[1] = *(const float2*)(fb + s * 512 + 64);
            MMA8(a, b);
        }
    };

    // ---------- Layer 2 ----------
    write_h(b1 + ne * 64);
    __syncthreads();
    gemm_sm(g_W2F + (size_t)ne * 4096);
    __syncthreads();

    // ---------- Layer 3 ----------
    write_h(b2 + ne * 64);
    __syncthreads();
    gemm_sm(g_W3F + (size_t)ne * 4096);
    __syncthreads();

    // ---------- epilogue: err = mean_d (pred - y)^2 ----------
    {
        float* errbuf = sm;          // [128][4]
        errbuf[tid] = 0.f;
        errbuf[tid + 256] = 0.f;
        __syncthreads();

        const float* b3p = b3 + ne * 64;
        #pragma unroll
        for (int i = 0; i < 4; ++i) {
            #pragma unroll
            for (int half = 0; half < 2; ++half) {
                const int rloc = wm * 64 + i * 16 + lr + half * 8;
                const int mg = mBase + rloc;
                float s_ = 0.f;
                if (mg < MTOT_) {
                    int bb = mg / TW_, tt = mg - bb * TW_;
                    const float* y = x + ((size_t)(bb * 64 + tt + 2) * N_ + n) * 64;
                    #pragma unroll
                    for (int nf = 0; nf < 2; ++nf) {
                        const int col = wn * 16 + nf * 8 + 2 * lc;
                        float p0 = C[i][nf][half * 2 + 0] + b3p[col];
                        float p1 = C[i][nf][half * 2 + 1] + b3p[col + 1];
                        float d0 = p0 - y[col];
                        float d1 = p1 - y[col + 1];
                        s_ += d0 * d0 + d1 * d1;
                    }
                }
                s_ += __shfl_xor_sync(0xffffffffu, s_, 1);
                s_ += __shfl_xor_sync(0xffffffffu, s_, 2);
                if (lc == 0) errbuf[rloc * 4 + wn] = s_;
            }
        }
        __syncthreads();
        if (tid < 128) {
            int mg = mBase + tid;
            if (mg < MTOT_) {
                float s_ = errbuf[tid * 4] + errbuf[tid * 4 + 1] + errbuf[tid * 4 + 2] + errbuf[tid * 4 + 3];
                g_err[(mg * N_ + n) * E_ + e] = s_ * (1.f / 64.f);
            }
        }
    }
}

// ---------------- reduction stage 1 ----------------
__global__ __launch_bounds__(256) void moe_red_part()
{
    __shared__ float red[256];
    const int tid = threadIdx.x;
    const int r = blockIdx.x * 256 + tid;
    float local = 0.f;
    if (r < MTOT_ * N_) {
        const float* ep = g_err + r * E_;
        float v[8];
        #pragma unroll
        for (int i = 0; i < 8; ++i) v[i] = ep[i];
        float mn = v[0];
        #pragma unroll
        for (int i = 1; i < 8; ++i) mn = fminf(mn, v[i]);
        float ex[8]; float Z = 0.f;
        #pragma unroll
        for (int i = 0; i < 8; ++i) { ex[i] = expf(mn - v[i]); Z += ex[i]; }
        float inv = 1.f / Z;
        float kl = 0.f;
        #pragma unroll
        for (int i = 0; i < 8; ++i) {
            float p = ex[i] * inv;
            kl += p * (logf(p + 1e-9f) + 2.0794415416798357f);
        }
        local = mn + 0.01f * kl;
    }
    red[tid] = local;
    __syncthreads();
    for (int s = 128; s > 0; s >>= 1) {
        if (tid < s) red[tid] += red[tid + s];
        __syncthreads();
    }
    if (tid == 0) g_part[blockIdx.x] = red[0];
}

// ---------------- reduction stage 2 ----------------
__global__ __launch_bounds__(128) void moe_red_final(float* __restrict__ out)
{
    __shared__ float red[128];
    const int tid = threadIdx.x;
    red[tid] = (tid < NB_RED) ? g_part[tid] : 0.f;
    __syncthreads();
    for (int s = 64; s > 0; s >>= 1) {
        if (tid < s) red[tid] += red[tid + s];
        __syncthreads();
    }
    if (tid == 0) out[0] = red[0] * (1.0f / 20160.0f);
    if (tid < B_) {
        int m = tid * TW_ + (TW_ - 1);
        const float* ep = g_err + (m * N_ + (N_ - 1)) * E_;
        float best = ep[0]; int bi = 0;
        #pragma unroll
        for (int i = 1; i < 8; ++i) {
            float vv = ep[i];
            if (vv < best) { best = vv; bi = i; }
        }
        out[1 + tid] = (float)bi;
    }
}

extern "C" void kernel_launch(void* const* d_in, const int* in_sizes, int n_in,
                              void* d_out, int out_size)
{
    const float* x  = (const float*)d_in[0];
    const int*   nb = (const int*)d_in[1];
    const float* W1 = (const float*)d_in[2];
    const float* b1 = (const float*)d_in[3];
    const float* W2 = (const float*)d_in[4];
    const float* b2 = (const float*)d_in[5];
    const float* W3 = (const float*)d_in[6];
    const float* b3 = (const float*)d_in[7];
    float* out = (float*)d_out;

    fgen<<<28160, 256>>>(x, nb);
    wtrans<<<30976, 256>>>(W1, W2, W3);

    size_t smem = 8192 * sizeof(float);
    cudaFuncSetAttribute(moe_main, cudaFuncAttributeMaxDynamicSharedMemorySize, (int)smem);
    moe_main<<<dim3(NE_, MT_), 256, smem>>>(x, b1, b2, b3);

    moe_red_part<<<NB_RED, 256>>>();
    moe_red_final<<<1, 128>>>(out);
}